// round 15
// baseline (speedup 1.0000x reference)
#include <cuda_runtime.h>
#include <cstdint>

// GeometricLoss, R15: R12 smem-grid + R6 distributed warp top-6.
//  K1 build (1 CTA): stats -> 48x48 sigma-clamped grid -> count -> scan ->
//     scatter g_pts4 {x,y,pid,0} + g_cellinfo {start,count}.
//  K2 search: 148 CTAs x 1024 (1/SM), all points+cells in smem; one warp per
//     binned query (grid-stride). Distributed top-6 (lane r holds rank r),
//     ballot-gated inserts w/ exact full-key gate + dup vote; disk scans as
//     flattened row ranges; jump expansion with exact termination bound.
// Exact jax.lax.top_k semantics (unique keys (d2_bits<<32)|pid, low-index
// tie-break); deterministic output (pid-indexed partials, fixed-order sum).

#define NPTS 8192
#define NCH 16
#define KNN 5
#define G 48
#define NCELL (G * G)          // 2304
#define FULLM 0xFFFFFFFFu
typedef unsigned long long ull;
#define SENT 0xFFFFFFFFFFFFFFFFULL
#define FINF __int_as_float(0x7F800000)

__device__ float4 g_pts4[NPTS];       // {x, y, bitcast(pid), 0}
__device__ int2   g_cellinfo[NCELL];  // {start, count}
__device__ float  g_partial[NPTS];    // indexed by ORIGINAL pid
__device__ unsigned g_ticket;
__device__ float g_minx, g_miny, g_invw, g_invh, g_cwmin;

// ======================= K1: build (single CTA) =======================
__global__ __launch_bounds__(1024, 1)
void build_kernel(const float2* __restrict__ pts) {
    __shared__ int   s_cnt[3072];
    __shared__ int   s_start[3072];
    __shared__ int   s_wsum[32];
    __shared__ float s_red[128];
    __shared__ float s_stat[128];
    __shared__ float s_minx, s_miny, s_invw, s_invh;

    const int tid = threadIdx.x;
    const int lane = tid & 31, warp = tid >> 5;

#pragma unroll
    for (int i = 0; i < 3; i++) s_cnt[tid + i * 1024] = 0;
    if (tid == 0) g_ticket = 0;

    float2 loc[NPTS / 1024];
    float mnx = 1e30f, mxx = -1e30f, mny = 1e30f, mxy = -1e30f;
    float sx = 0.f, sy = 0.f, sxx = 0.f, syy = 0.f;
#pragma unroll
    for (int i = 0; i < NPTS / 1024; i++) {
        float2 p = pts[tid + i * 1024];
        loc[i] = p;
        mnx = fminf(mnx, p.x); mxx = fmaxf(mxx, p.x);
        mny = fminf(mny, p.y); mxy = fmaxf(mxy, p.y);
        sx += p.x; sy += p.y;
        sxx = fmaf(p.x, p.x, sxx); syy = fmaf(p.y, p.y, syy);
    }
#pragma unroll
    for (int off = 16; off > 0; off >>= 1) {
        mnx = fminf(mnx, __shfl_xor_sync(FULLM, mnx, off));
        mxx = fmaxf(mxx, __shfl_xor_sync(FULLM, mxx, off));
        mny = fminf(mny, __shfl_xor_sync(FULLM, mny, off));
        mxy = fmaxf(mxy, __shfl_xor_sync(FULLM, mxy, off));
        sx  += __shfl_xor_sync(FULLM, sx,  off);
        sy  += __shfl_xor_sync(FULLM, sy,  off);
        sxx += __shfl_xor_sync(FULLM, sxx, off);
        syy += __shfl_xor_sync(FULLM, syy, off);
    }
    if (lane == 0) {
        s_red[warp] = mnx; s_red[32 + warp] = mxx;
        s_red[64 + warp] = mny; s_red[96 + warp] = mxy;
        s_stat[warp] = sx; s_stat[32 + warp] = sy;
        s_stat[64 + warp] = sxx; s_stat[96 + warp] = syy;
    }
    __syncthreads();
    if (warp == 0) {
        float a = s_red[lane], bx = s_red[32 + lane];
        float c = s_red[64 + lane], dym = s_red[96 + lane];
        float tx = s_stat[lane], ty = s_stat[32 + lane];
        float txx = s_stat[64 + lane], tyy = s_stat[96 + lane];
#pragma unroll
        for (int off = 16; off > 0; off >>= 1) {
            a   = fminf(a,   __shfl_xor_sync(FULLM, a,   off));
            bx  = fmaxf(bx,  __shfl_xor_sync(FULLM, bx,  off));
            c   = fminf(c,   __shfl_xor_sync(FULLM, c,   off));
            dym = fmaxf(dym, __shfl_xor_sync(FULLM, dym, off));
            tx  += __shfl_xor_sync(FULLM, tx,  off);
            ty  += __shfl_xor_sync(FULLM, ty,  off);
            txx += __shfl_xor_sync(FULLM, txx, off);
            tyy += __shfl_xor_sync(FULLM, tyy, off);
        }
        if (lane == 0) {
            const float invn = 1.0f / (float)NPTS;
            float mx = tx * invn, my = ty * invn;
            float vx = fmaxf(txx * invn - mx * mx, 0.0f);
            float vy = fmaxf(tyy * invn - my * my, 0.0f);
            float sdx = sqrtf(vx), sdy = sqrtf(vy);
            float lox = fmaxf(a,   mx - 2.5f * sdx);
            float hix = fminf(bx,  mx + 2.5f * sdx);
            float loy = fmaxf(c,   my - 2.5f * sdy);
            float hiy = fminf(dym, my + 2.5f * sdy);
            if (!(hix > lox)) { lox = a; hix = bx; }
            if (!(hiy > loy)) { loy = c; hiy = dym; }
            float w = hix - lox, h = hiy - loy;
            s_minx = lox; g_minx = lox;
            s_miny = loy; g_miny = loy;
            float iw = (w > 0.0f) ? (float)G / w : 0.0f;
            float ih = (h > 0.0f) ? (float)G / h : 0.0f;
            s_invw = iw; g_invw = iw;
            s_invh = ih; g_invh = ih;
            g_cwmin = fminf(w / (float)G, h / (float)G);
        }
    }
    __syncthreads();

    int mycell[NPTS / 1024];
#pragma unroll
    for (int i = 0; i < NPTS / 1024; i++) {
        int cx = min(max((int)((loc[i].x - s_minx) * s_invw), 0), G - 1);
        int cy = min(max((int)((loc[i].y - s_miny) * s_invh), 0), G - 1);
        int c = cy * G + cx;
        mycell[i] = c;
        atomicAdd(&s_cnt[c], 1);
    }
    __syncthreads();

    int v[3], run = 0;
    const int base = tid * 3;
#pragma unroll
    for (int i = 0; i < 3; i++) { v[i] = run; run += s_cnt[base + i]; }
    int inc = run;
#pragma unroll
    for (int off = 1; off < 32; off <<= 1) {
        int y = __shfl_up_sync(FULLM, inc, off);
        if (lane >= off) inc += y;
    }
    if (lane == 31) s_wsum[warp] = inc;
    __syncthreads();
    if (warp == 0) {
        int x = s_wsum[lane];
#pragma unroll
        for (int off = 1; off < 32; off <<= 1) {
            int y = __shfl_up_sync(FULLM, x, off);
            if (lane >= off) x += y;
        }
        s_wsum[lane] = x;
    }
    __syncthreads();
    int pre = ((warp > 0) ? s_wsum[warp - 1] : 0) + inc - run;
#pragma unroll
    for (int i = 0; i < 3; i++) {
        int st = pre + v[i];
        s_start[base + i] = st;
        if (base + i < NCELL)
            g_cellinfo[base + i] = make_int2(st, s_cnt[base + i]);
    }
    __syncthreads();

#pragma unroll
    for (int i = 0; i < NPTS / 1024; i++) {
        int slot = atomicAdd(&s_start[mycell[i]], 1);
        g_pts4[slot] = make_float4(loc[i].x, loc[i].y,
                                   __int_as_float(tid + i * 1024), 0.0f);
    }
}

// ======================= K2: search =======================
#define STPB 1024
#define SNBLK 148
#define NWARPS (SNBLK * (STPB / 32))   // 4736

extern __shared__ char smem_dyn[];     // float4 s_pts[NPTS] + int2 s_cell[NCELL]

// Scan full Chebyshev disk of radius D as flattened per-row ranges, updating
// the distributed top-6 (key: lane r holds rank r). Exact gate nk < rank5
// full key; duplicate vote makes rescans safe.
__device__ __forceinline__ void scan_disk(
    int D, int cx, int cy, float qx, float qy,
    const float4* s_pts, const int2* s_cell,
    ull& key, ull& th_key, float& th_f, int lane) {
    int xa = max(cx - D, 0), xb = min(cx + D, G - 1);
    int ya = max(cy - D, 0), yb = min(cy + D, G - 1);
    for (int y = ya; y <= yb; y++) {
        int2 c0 = s_cell[y * G + xa];
        int2 c1 = s_cell[y * G + xb];
        int e = c1.x + c1.y;
        for (int j0 = c0.x; j0 < e; j0 += 32) {
            int j = j0 + lane;
            float d2 = FINF;
            unsigned p = 0;
            if (j < e) {
                float4 P = s_pts[j];
                float dx = qx - P.x, dy = qy - P.y;
                d2 = fmaf(dx, dx, dy * dy);
                p = (unsigned)__float_as_int(P.z);
            }
            unsigned msk = __ballot_sync(FULLM, d2 <= th_f);
            while (msk) {
                int src = __ffs(msk) - 1;
                msk &= msk - 1;
                float dd = __shfl_sync(FULLM, d2, src);
                unsigned pp = __shfl_sync(FULLM, p, src);
                ull nk = ((ull)__float_as_uint(dd) << 32) | pp;
                bool dup = __any_sync(FULLM, (lane < 6) && (key == nk));
                if (!dup && nk < th_key) {     // uniform branch
                    ull prev = __shfl_up_sync(FULLM, key, 1);
                    bool shift = (lane > 0) && (nk < prev);
                    bool take = nk < key;
                    key = shift ? prev : (take ? nk : key);
                    th_key = __shfl_sync(FULLM, key, 5);
                    unsigned h = (unsigned)(th_key >> 32);
                    th_f = (h >= 0x7F800000u) ? FINF : __uint_as_float(h);
                }
            }
        }
    }
}

__global__ __launch_bounds__(STPB, 1)
void search_kernel(const float* __restrict__ outputs,
                   float* __restrict__ out) {
    float4* s_pts  = (float4*)smem_dyn;
    int2*   s_cell = (int2*)(smem_dyn + NPTS * sizeof(float4));

    const int tid = threadIdx.x;
    const int lane = tid & 31;
    const int gwarp = blockIdx.x * (STPB / 32) + (tid >> 5);

    for (int i = tid; i < NPTS; i += STPB) s_pts[i] = g_pts4[i];
    for (int i = tid; i < NCELL; i += STPB) s_cell[i] = g_cellinfo[i];
    __syncthreads();

    const float minx = g_minx, miny = g_miny;
    const float invw = g_invw, invh = g_invh;
    const float cw = g_cwmin;

    for (int q = gwarp; q < NPTS; q += NWARPS) {
        const float4 Q = s_pts[q];
        const float qx = Q.x, qy = Q.y;
        const unsigned qpid = (unsigned)__float_as_int(Q.z);
        const int cx = min(max((int)((qx - minx) * invw), 0), G - 1);
        const int cy = min(max((int)((qy - miny) * invh), 0), G - 1);

        ull key = SENT, th_key = SENT;
        float th_f = FINF;

        scan_disk(1, cx, cy, qx, qy, s_pts, s_cell, key, th_key, th_f, lane);
        int D = 1;
        while (D < G) {
            float bnd = (float)D * cw;
            if (th_f <= bnd * bnd) break;   // unscanned cells >= D*cw away
            int Dn;
            if (th_key != SENT) {           // have 6: one terminal jump
                Dn = (int)ceilf(sqrtf(th_f) / fmaxf(cw, 1e-30f));
            } else {
                Dn = 2 * D;                 // still filling: double
            }
            Dn = max(Dn, D + 1);
            Dn = min(Dn, (int)G);
            scan_disk(Dn, cx, cy, qx, qy, s_pts, s_cell,
                      key, th_key, th_f, lane);
            D = Dn;
        }

        // epilogue: lane 0 = self (d2=0 min key); lanes 1..5 = neighbors
        float s = 0.0f;
        if (lane >= 1 && lane <= KNN) {
            int nb = (int)(key & 0xFFFFFFFFULL);
            const float4* oq = (const float4*)(outputs + (size_t)qpid * NCH);
            const float4* on = (const float4*)(outputs + (size_t)nb * NCH);
            float acc = 0.0f;
#pragma unroll
            for (int c = 0; c < NCH / 4; c++) {
                float4 a = oq[c];
                float4 bb = on[c];
                float d;
                d = a.x - bb.x; acc = fmaf(d, d, acc);
                d = a.y - bb.y; acc = fmaf(d, d, acc);
                d = a.z - bb.z; acc = fmaf(d, d, acc);
                d = a.w - bb.w; acc = fmaf(d, d, acc);
            }
            s = sqrtf(acc);
        }
#pragma unroll
        for (int off = 16; off > 0; off >>= 1)
            s += __shfl_xor_sync(FULLM, s, off);
        if (lane == 0) g_partial[qpid] = s;
    }

    // ---- fused final reduction: last CTA, fixed order ----
    __syncthreads();
    __shared__ bool is_last;
    if (tid == 0) {
        __threadfence();
        unsigned tk = atomicAdd(&g_ticket, 1);
        is_last = (tk == SNBLK - 1);
    }
    __syncthreads();
    if (is_last) {
        __threadfence();
        float acc = 0.0f;
        for (int j = tid; j < NPTS; j += STPB) acc += g_partial[j];
        __shared__ float sm[STPB];
        sm[tid] = acc;
        __syncthreads();
        for (int st = STPB / 2; st > 0; st >>= 1) {
            if (tid < st) sm[tid] += sm[tid + st];
            __syncthreads();
        }
        if (tid == 0) {
            out[0] = sm[0] / (float)(NPTS * KNN);
            g_ticket = 0;   // reset for next graph replay
        }
    }
}

extern "C" void kernel_launch(void* const* d_in, const int* in_sizes, int n_in,
                              void* d_out, int out_size) {
    const float*  outputs = (const float*)d_in[0];
    const float2* points  = (const float2*)d_in[1];
    float* out = (float*)d_out;

    const int smem_bytes = NPTS * sizeof(float4) + NCELL * sizeof(int2);
    cudaFuncSetAttribute(search_kernel,
                         cudaFuncAttributeMaxDynamicSharedMemorySize,
                         smem_bytes);
    build_kernel<<<1, 1024>>>(points);
    search_kernel<<<SNBLK, STPB, smem_bytes>>>(outputs, out);
}

// round 16
// speedup vs baseline: 3.7153x; 3.7153x over previous
#include <cuda_runtime.h>
#include <cstdint>

// GeometricLoss, R16: R12 smem-grid search + lazy REDUX selection.
//  K1 build (1 CTA): stats -> 48x48 sigma-clamped grid -> count -> scan ->
//     scatter g_pts4 {x,y,pid,0} + g_cellinfo {start,count}.
//  K2 search: 148 CTAs x 1024 (1/SM), all points+cells in smem; one warp per
//     binned query (grid-stride). Per-lane exact top-6 lists; warp-uniform
//     UPPER BOUND on the 6th-best d2 (6x reduce_min over lane minima; provably
//     >= v6) used for gating + exact ring termination; ONE exact two-phase
//     REDUX extraction per query at the end.
// Keys (d2_bits<<32)|pid unique & totally ordered -> order-independent exact
// selection, jax.lax.top_k low-index tie-break, deterministic output.

#define NPTS 8192
#define NCH 16
#define KNN 5
#define G 48
#define NCELL (G * G)          // 2304
#define FULLM 0xFFFFFFFFu
typedef unsigned long long ull;
#define SENT 0xFFFFFFFFFFFFFFFFULL
#define FINF __int_as_float(0x7F800000)

__device__ float4 g_pts4[NPTS];       // {x, y, bitcast(pid), 0}
__device__ int2   g_cellinfo[NCELL];  // {start, count}
__device__ float  g_partial[NPTS];    // indexed by ORIGINAL pid
__device__ unsigned g_ticket;
__device__ float g_minx, g_miny, g_invw, g_invh, g_cwmin;

// ======================= K1: build (single CTA) =======================
__global__ __launch_bounds__(1024, 1)
void build_kernel(const float2* __restrict__ pts) {
    __shared__ int   s_cnt[3072];
    __shared__ int   s_start[3072];
    __shared__ int   s_wsum[32];
    __shared__ float s_red[128];
    __shared__ float s_stat[128];
    __shared__ float s_minx, s_miny, s_invw, s_invh;

    const int tid = threadIdx.x;
    const int lane = tid & 31, warp = tid >> 5;

#pragma unroll
    for (int i = 0; i < 3; i++) s_cnt[tid + i * 1024] = 0;
    if (tid == 0) g_ticket = 0;

    float2 loc[NPTS / 1024];
    float mnx = 1e30f, mxx = -1e30f, mny = 1e30f, mxy = -1e30f;
    float sx = 0.f, sy = 0.f, sxx = 0.f, syy = 0.f;
#pragma unroll
    for (int i = 0; i < NPTS / 1024; i++) {
        float2 p = pts[tid + i * 1024];
        loc[i] = p;
        mnx = fminf(mnx, p.x); mxx = fmaxf(mxx, p.x);
        mny = fminf(mny, p.y); mxy = fmaxf(mxy, p.y);
        sx += p.x; sy += p.y;
        sxx = fmaf(p.x, p.x, sxx); syy = fmaf(p.y, p.y, syy);
    }
#pragma unroll
    for (int off = 16; off > 0; off >>= 1) {
        mnx = fminf(mnx, __shfl_xor_sync(FULLM, mnx, off));
        mxx = fmaxf(mxx, __shfl_xor_sync(FULLM, mxx, off));
        mny = fminf(mny, __shfl_xor_sync(FULLM, mny, off));
        mxy = fmaxf(mxy, __shfl_xor_sync(FULLM, mxy, off));
        sx  += __shfl_xor_sync(FULLM, sx,  off);
        sy  += __shfl_xor_sync(FULLM, sy,  off);
        sxx += __shfl_xor_sync(FULLM, sxx, off);
        syy += __shfl_xor_sync(FULLM, syy, off);
    }
    if (lane == 0) {
        s_red[warp] = mnx; s_red[32 + warp] = mxx;
        s_red[64 + warp] = mny; s_red[96 + warp] = mxy;
        s_stat[warp] = sx; s_stat[32 + warp] = sy;
        s_stat[64 + warp] = sxx; s_stat[96 + warp] = syy;
    }
    __syncthreads();
    if (warp == 0) {
        float a = s_red[lane], bx = s_red[32 + lane];
        float c = s_red[64 + lane], dym = s_red[96 + lane];
        float tx = s_stat[lane], ty = s_stat[32 + lane];
        float txx = s_stat[64 + lane], tyy = s_stat[96 + lane];
#pragma unroll
        for (int off = 16; off > 0; off >>= 1) {
            a   = fminf(a,   __shfl_xor_sync(FULLM, a,   off));
            bx  = fmaxf(bx,  __shfl_xor_sync(FULLM, bx,  off));
            c   = fminf(c,   __shfl_xor_sync(FULLM, c,   off));
            dym = fmaxf(dym, __shfl_xor_sync(FULLM, dym, off));
            tx  += __shfl_xor_sync(FULLM, tx,  off);
            ty  += __shfl_xor_sync(FULLM, ty,  off);
            txx += __shfl_xor_sync(FULLM, txx, off);
            tyy += __shfl_xor_sync(FULLM, tyy, off);
        }
        if (lane == 0) {
            const float invn = 1.0f / (float)NPTS;
            float mx = tx * invn, my = ty * invn;
            float vx = fmaxf(txx * invn - mx * mx, 0.0f);
            float vy = fmaxf(tyy * invn - my * my, 0.0f);
            float sdx = sqrtf(vx), sdy = sqrtf(vy);
            float lox = fmaxf(a,   mx - 2.5f * sdx);
            float hix = fminf(bx,  mx + 2.5f * sdx);
            float loy = fmaxf(c,   my - 2.5f * sdy);
            float hiy = fminf(dym, my + 2.5f * sdy);
            if (!(hix > lox)) { lox = a; hix = bx; }
            if (!(hiy > loy)) { loy = c; hiy = dym; }
            float w = hix - lox, h = hiy - loy;
            s_minx = lox; g_minx = lox;
            s_miny = loy; g_miny = loy;
            float iw = (w > 0.0f) ? (float)G / w : 0.0f;
            float ih = (h > 0.0f) ? (float)G / h : 0.0f;
            s_invw = iw; g_invw = iw;
            s_invh = ih; g_invh = ih;
            g_cwmin = fminf(w / (float)G, h / (float)G);
        }
    }
    __syncthreads();

    int mycell[NPTS / 1024];
#pragma unroll
    for (int i = 0; i < NPTS / 1024; i++) {
        int cx = min(max((int)((loc[i].x - s_minx) * s_invw), 0), G - 1);
        int cy = min(max((int)((loc[i].y - s_miny) * s_invh), 0), G - 1);
        int c = cy * G + cx;
        mycell[i] = c;
        atomicAdd(&s_cnt[c], 1);
    }
    __syncthreads();

    int v[3], run = 0;
    const int base = tid * 3;
#pragma unroll
    for (int i = 0; i < 3; i++) { v[i] = run; run += s_cnt[base + i]; }
    int inc = run;
#pragma unroll
    for (int off = 1; off < 32; off <<= 1) {
        int y = __shfl_up_sync(FULLM, inc, off);
        if (lane >= off) inc += y;
    }
    if (lane == 31) s_wsum[warp] = inc;
    __syncthreads();
    if (warp == 0) {
        int x = s_wsum[lane];
#pragma unroll
        for (int off = 1; off < 32; off <<= 1) {
            int y = __shfl_up_sync(FULLM, x, off);
            if (lane >= off) x += y;
        }
        s_wsum[lane] = x;
    }
    __syncthreads();
    int pre = ((warp > 0) ? s_wsum[warp - 1] : 0) + inc - run;
#pragma unroll
    for (int i = 0; i < 3; i++) {
        int st = pre + v[i];
        s_start[base + i] = st;
        if (base + i < NCELL)
            g_cellinfo[base + i] = make_int2(st, s_cnt[base + i]);
    }
    __syncthreads();

#pragma unroll
    for (int i = 0; i < NPTS / 1024; i++) {
        int slot = atomicAdd(&s_start[mycell[i]], 1);
        g_pts4[slot] = make_float4(loc[i].x, loc[i].y,
                                   __int_as_float(tid + i * 1024), 0.0f);
    }
}

// ======================= K2: search =======================
#define STPB 1024
#define SNBLK 148
#define NWARPS (SNBLK * (STPB / 32))   // 4736

extern __shared__ char smem_dyn[];     // float4 s_pts[NPTS] + int2 s_cell[NCELL]

// Per-lane sorted top-6 insert (exact per-lane; no warp interaction).
__device__ __forceinline__ void ins6(ull* b, float d2, unsigned pid) {
    ull key = ((ull)__float_as_uint(d2) << 32) | pid;
    if (key < b[5]) {
        b[5] = key;
#pragma unroll
        for (int t = 5; t > 0; t--) {
            if (b[t] < b[t - 1]) { ull tmp = b[t]; b[t] = b[t - 1]; b[t - 1] = tmp; }
        }
    }
}

// Warp-uniform UPPER BOUND on the global 6th-best d2: 6th smallest of the 32
// lane minima (>= v6: if 6 lane minima were < v6, 6 distinct values < v6 —
// contradiction). Ties self-exclude together -> bound only grows -> safe.
__device__ __forceinline__ float ub6(const ull* b) {
    unsigned v = (unsigned)(b[0] >> 32);
    unsigned m = 0;
#pragma unroll
    for (int r = 0; r < 6; r++) {
        m = __reduce_min_sync(FULLM, v);
        if (v == m) v = 0xFFFFFFFFu;
    }
    return (m >= 0x7F800000u) ? FINF : __uint_as_float(m);
}

// Exact final extraction: 6 rounds of two-phase REDUX (min d2-bits, then min
// pid among ties). Unique keys -> exactly one owner shifts. Lane r -> rank r.
__device__ __forceinline__ ull extract_rank(ull* b, int lane) {
    ull myrk = SENT;
#pragma unroll
    for (int r = 0; r < 6; r++) {
        unsigned hi = (unsigned)(b[0] >> 32);
        unsigned mhi = __reduce_min_sync(FULLM, hi);
        unsigned lo = (hi == mhi) ? (unsigned)(b[0] & 0xFFFFFFFFULL)
                                  : 0xFFFFFFFFu;
        unsigned mlo = __reduce_min_sync(FULLM, lo);
        ull win = ((ull)mhi << 32) | mlo;
        if (lane == r) myrk = win;
        if (b[0] == win) {
            b[0] = b[1]; b[1] = b[2]; b[2] = b[3];
            b[3] = b[4]; b[4] = b[5]; b[5] = SENT;
        }
    }
    return myrk;
}

__global__ __launch_bounds__(STPB, 1)
void search_kernel(const float* __restrict__ outputs,
                   float* __restrict__ out) {
    float4* s_pts  = (float4*)smem_dyn;
    int2*   s_cell = (int2*)(smem_dyn + NPTS * sizeof(float4));

    const int tid = threadIdx.x;
    const int lane = tid & 31;
    const int gwarp = blockIdx.x * (STPB / 32) + (tid >> 5);

    for (int i = tid; i < NPTS; i += STPB) s_pts[i] = g_pts4[i];
    for (int i = tid; i < NCELL; i += STPB) s_cell[i] = g_cellinfo[i];
    __syncthreads();

    const float minx = g_minx, miny = g_miny;
    const float invw = g_invw, invh = g_invh;
    const float cw = g_cwmin;

    for (int q = gwarp; q < NPTS; q += NWARPS) {
        const float4 Q = s_pts[q];
        const float qx = Q.x, qy = Q.y;
        const unsigned qpid = (unsigned)__float_as_int(Q.z);
        const int cx = min(max((int)((qx - minx) * invw), 0), G - 1);
        const int cy = min(max((int)((qy - miny) * invh), 0), G - 1);

        ull b[6];
#pragma unroll
        for (int t = 0; t < 6; t++) b[t] = SENT;

        // ---- disk D=1: flattened union of <=3 contiguous row ranges ----
        {
            int xa = max(cx - 1, 0), xb = min(cx + 1, G - 1);
            int ya = max(cy - 1, 0), yb = min(cy + 1, G - 1);
            int s0 = 0, l0 = 0, s1 = 0, l1 = 0, s2 = 0, l2 = 0;
            {
                int2 c0 = s_cell[ya * G + xa];
                int2 c1 = s_cell[ya * G + xb];
                s0 = c0.x; l0 = c1.x + c1.y - c0.x;
            }
            if (ya + 1 <= yb) {
                int2 c0 = s_cell[(ya + 1) * G + xa];
                int2 c1 = s_cell[(ya + 1) * G + xb];
                s1 = c0.x; l1 = c1.x + c1.y - c0.x;
            }
            if (ya + 2 <= yb) {
                int2 c0 = s_cell[(ya + 2) * G + xa];
                int2 c1 = s_cell[(ya + 2) * G + xb];
                s2 = c0.x; l2 = c1.x + c1.y - c0.x;
            }
            int o1 = l0, o2 = l0 + l1, tot = o2 + l2;
            for (int t = lane; t < tot; t += 32) {
                int j;
                if (t < o1)      j = s0 + t;
                else if (t < o2) j = s1 + (t - o1);
                else             j = s2 + (t - o2);
                float4 P = s_pts[j];
                float dx = qx - P.x, dy = qy - P.y;
                float d2 = fmaf(dx, dx, dy * dy);
                ins6(b, d2, (unsigned)__float_as_int(P.z));
            }
        }
        float th = ub6(b);   // warp-uniform upper bound on v6

        // ---- expanding rings, lane-per-cell, ub-gated termination ----
        int D = 1;
        while (D < G) {
            float bnd = (float)D * cw;
            if (th <= bnd * bnd) break;   // ub >= v6 -> exact termination
            const int d = D + 1;
            const int ncells = 8 * d;
            bool dirty = false;
            for (int tb = 0; tb < ncells; tb += 32) {
                int t = tb + lane;
                if (t < ncells) {
                    int x, y;
                    int rowspan = 2 * d + 1;
                    if (t < 2 * rowspan) {
                        int row = t / rowspan, k = t % rowspan;
                        x = cx - d + k;
                        y = row ? cy + d : cy - d;
                    } else {
                        int t2 = t - 2 * rowspan;
                        int colspan = 2 * d - 1;
                        int col = t2 / colspan, k = t2 % colspan;
                        x = col ? cx + d : cx - d;
                        y = cy - d + 1 + k;
                    }
                    if ((unsigned)x < G && (unsigned)y < G) {
                        int2 ci = s_cell[y * G + x];
                        int e = ci.x + ci.y;
                        for (int j = ci.x; j < e; j++) {
                            float4 P = s_pts[j];
                            float dx = qx - P.x, dy = qy - P.y;
                            float d2 = fmaf(dx, dx, dy * dy);
                            if (d2 <= th) {   // ub gate: conservative, safe
                                ins6(b, d2, (unsigned)__float_as_int(P.z));
                                dirty = true;
                            }
                        }
                    }
                }
            }
            if (__ballot_sync(FULLM, dirty)) th = ub6(b);
            D = d;
        }

        // ---- exact extraction once; rank 0 = self; lanes 1..5 = nbrs ----
        ull myrk = extract_rank(b, lane);
        float s = 0.0f;
        if (lane >= 1 && lane <= KNN) {
            int nb = (int)(myrk & 0xFFFFFFFFULL);
            const float4* oq = (const float4*)(outputs + (size_t)qpid * NCH);
            const float4* on = (const float4*)(outputs + (size_t)nb * NCH);
            float acc = 0.0f;
#pragma unroll
            for (int c = 0; c < NCH / 4; c++) {
                float4 a = oq[c];
                float4 bb = on[c];
                float d;
                d = a.x - bb.x; acc = fmaf(d, d, acc);
                d = a.y - bb.y; acc = fmaf(d, d, acc);
                d = a.z - bb.z; acc = fmaf(d, d, acc);
                d = a.w - bb.w; acc = fmaf(d, d, acc);
            }
            s = sqrtf(acc);
        }
#pragma unroll
        for (int off = 16; off > 0; off >>= 1)
            s += __shfl_xor_sync(FULLM, s, off);
        if (lane == 0) g_partial[qpid] = s;
    }

    // ---- fused final reduction: last CTA, fixed order ----
    __syncthreads();
    __shared__ bool is_last;
    if (tid == 0) {
        __threadfence();
        unsigned tk = atomicAdd(&g_ticket, 1);
        is_last = (tk == SNBLK - 1);
    }
    __syncthreads();
    if (is_last) {
        __threadfence();
        float acc = 0.0f;
        for (int j = tid; j < NPTS; j += STPB) acc += g_partial[j];
        __shared__ float sm[STPB];
        sm[tid] = acc;
        __syncthreads();
        for (int st = STPB / 2; st > 0; st >>= 1) {
            if (tid < st) sm[tid] += sm[tid + st];
            __syncthreads();
        }
        if (tid == 0) {
            out[0] = sm[0] / (float)(NPTS * KNN);
            g_ticket = 0;   // reset for next graph replay
        }
    }
}

extern "C" void kernel_launch(void* const* d_in, const int* in_sizes, int n_in,
                              void* d_out, int out_size) {
    const float*  outputs = (const float*)d_in[0];
    const float2* points  = (const float2*)d_in[1];
    float* out = (float*)d_out;

    const int smem_bytes = NPTS * sizeof(float4) + NCELL * sizeof(int2);
    cudaFuncSetAttribute(search_kernel,
                         cudaFuncAttributeMaxDynamicSharedMemorySize,
                         smem_bytes);
    build_kernel<<<1, 1024>>>(points);
    search_kernel<<<SNBLK, STPB, smem_bytes>>>(outputs, out);
}

// round 17
// speedup vs baseline: 3.7384x; 1.0062x over previous
#include <cuda_runtime.h>
#include <cstdint>

// GeometricLoss, R17 = R16 + dynamic query scheduler + advancing ub6.
//  K1 build (1 CTA): stats -> 48x48 sigma-clamped grid -> count -> scan ->
//     scatter g_pts4 {x,y,pid,0} + g_cellinfo {start,count}; resets counters.
//  K2 search: 148 CTAs x 1024 (1/SM), all points+cells in smem; warps POP
//     queries from a global atomic counter (tail-balanced). Per-lane exact
//     top-6 lists; ADVANCING warp-uniform upper bound on v6 (6 REDUX rounds,
//     lanes advance within their sorted lists; ties advance together ->
//     bound >= v6, safe); ONE exact two-phase REDUX extraction per query.
// Keys (d2_bits<<32)|pid unique & totally ordered -> order-independent exact
// selection, jax.lax.top_k low-index tie-break, deterministic output.

#define NPTS 8192
#define NCH 16
#define KNN 5
#define G 48
#define NCELL (G * G)          // 2304
#define FULLM 0xFFFFFFFFu
typedef unsigned long long ull;
#define SENT 0xFFFFFFFFFFFFFFFFULL
#define FINF __int_as_float(0x7F800000)

__device__ float4 g_pts4[NPTS];       // {x, y, bitcast(pid), 0}
__device__ int2   g_cellinfo[NCELL];  // {start, count}
__device__ float  g_partial[NPTS];    // indexed by ORIGINAL pid
__device__ unsigned g_ticket;
__device__ unsigned g_qhead;          // dynamic query cursor
__device__ float g_minx, g_miny, g_invw, g_invh, g_cwmin;

// ======================= K1: build (single CTA) =======================
__global__ __launch_bounds__(1024, 1)
void build_kernel(const float2* __restrict__ pts) {
    __shared__ int   s_cnt[3072];
    __shared__ int   s_start[3072];
    __shared__ int   s_wsum[32];
    __shared__ float s_red[128];
    __shared__ float s_stat[128];
    __shared__ float s_minx, s_miny, s_invw, s_invh;

    const int tid = threadIdx.x;
    const int lane = tid & 31, warp = tid >> 5;

#pragma unroll
    for (int i = 0; i < 3; i++) s_cnt[tid + i * 1024] = 0;
    if (tid == 0) { g_ticket = 0; g_qhead = 0; }

    float2 loc[NPTS / 1024];
    float mnx = 1e30f, mxx = -1e30f, mny = 1e30f, mxy = -1e30f;
    float sx = 0.f, sy = 0.f, sxx = 0.f, syy = 0.f;
#pragma unroll
    for (int i = 0; i < NPTS / 1024; i++) {
        float2 p = pts[tid + i * 1024];
        loc[i] = p;
        mnx = fminf(mnx, p.x); mxx = fmaxf(mxx, p.x);
        mny = fminf(mny, p.y); mxy = fmaxf(mxy, p.y);
        sx += p.x; sy += p.y;
        sxx = fmaf(p.x, p.x, sxx); syy = fmaf(p.y, p.y, syy);
    }
#pragma unroll
    for (int off = 16; off > 0; off >>= 1) {
        mnx = fminf(mnx, __shfl_xor_sync(FULLM, mnx, off));
        mxx = fmaxf(mxx, __shfl_xor_sync(FULLM, mxx, off));
        mny = fminf(mny, __shfl_xor_sync(FULLM, mny, off));
        mxy = fmaxf(mxy, __shfl_xor_sync(FULLM, mxy, off));
        sx  += __shfl_xor_sync(FULLM, sx,  off);
        sy  += __shfl_xor_sync(FULLM, sy,  off);
        sxx += __shfl_xor_sync(FULLM, sxx, off);
        syy += __shfl_xor_sync(FULLM, syy, off);
    }
    if (lane == 0) {
        s_red[warp] = mnx; s_red[32 + warp] = mxx;
        s_red[64 + warp] = mny; s_red[96 + warp] = mxy;
        s_stat[warp] = sx; s_stat[32 + warp] = sy;
        s_stat[64 + warp] = sxx; s_stat[96 + warp] = syy;
    }
    __syncthreads();
    if (warp == 0) {
        float a = s_red[lane], bx = s_red[32 + lane];
        float c = s_red[64 + lane], dym = s_red[96 + lane];
        float tx = s_stat[lane], ty = s_stat[32 + lane];
        float txx = s_stat[64 + lane], tyy = s_stat[96 + lane];
#pragma unroll
        for (int off = 16; off > 0; off >>= 1) {
            a   = fminf(a,   __shfl_xor_sync(FULLM, a,   off));
            bx  = fmaxf(bx,  __shfl_xor_sync(FULLM, bx,  off));
            c   = fminf(c,   __shfl_xor_sync(FULLM, c,   off));
            dym = fmaxf(dym, __shfl_xor_sync(FULLM, dym, off));
            tx  += __shfl_xor_sync(FULLM, tx,  off);
            ty  += __shfl_xor_sync(FULLM, ty,  off);
            txx += __shfl_xor_sync(FULLM, txx, off);
            tyy += __shfl_xor_sync(FULLM, tyy, off);
        }
        if (lane == 0) {
            const float invn = 1.0f / (float)NPTS;
            float mx = tx * invn, my = ty * invn;
            float vx = fmaxf(txx * invn - mx * mx, 0.0f);
            float vy = fmaxf(tyy * invn - my * my, 0.0f);
            float sdx = sqrtf(vx), sdy = sqrtf(vy);
            float lox = fmaxf(a,   mx - 2.5f * sdx);
            float hix = fminf(bx,  mx + 2.5f * sdx);
            float loy = fmaxf(c,   my - 2.5f * sdy);
            float hiy = fminf(dym, my + 2.5f * sdy);
            if (!(hix > lox)) { lox = a; hix = bx; }
            if (!(hiy > loy)) { loy = c; hiy = dym; }
            float w = hix - lox, h = hiy - loy;
            s_minx = lox; g_minx = lox;
            s_miny = loy; g_miny = loy;
            float iw = (w > 0.0f) ? (float)G / w : 0.0f;
            float ih = (h > 0.0f) ? (float)G / h : 0.0f;
            s_invw = iw; g_invw = iw;
            s_invh = ih; g_invh = ih;
            g_cwmin = fminf(w / (float)G, h / (float)G);
        }
    }
    __syncthreads();

    int mycell[NPTS / 1024];
#pragma unroll
    for (int i = 0; i < NPTS / 1024; i++) {
        int cx = min(max((int)((loc[i].x - s_minx) * s_invw), 0), G - 1);
        int cy = min(max((int)((loc[i].y - s_miny) * s_invh), 0), G - 1);
        int c = cy * G + cx;
        mycell[i] = c;
        atomicAdd(&s_cnt[c], 1);
    }
    __syncthreads();

    int v[3], run = 0;
    const int base = tid * 3;
#pragma unroll
    for (int i = 0; i < 3; i++) { v[i] = run; run += s_cnt[base + i]; }
    int inc = run;
#pragma unroll
    for (int off = 1; off < 32; off <<= 1) {
        int y = __shfl_up_sync(FULLM, inc, off);
        if (lane >= off) inc += y;
    }
    if (lane == 31) s_wsum[warp] = inc;
    __syncthreads();
    if (warp == 0) {
        int x = s_wsum[lane];
#pragma unroll
        for (int off = 1; off < 32; off <<= 1) {
            int y = __shfl_up_sync(FULLM, x, off);
            if (lane >= off) x += y;
        }
        s_wsum[lane] = x;
    }
    __syncthreads();
    int pre = ((warp > 0) ? s_wsum[warp - 1] : 0) + inc - run;
#pragma unroll
    for (int i = 0; i < 3; i++) {
        int st = pre + v[i];
        s_start[base + i] = st;
        if (base + i < NCELL)
            g_cellinfo[base + i] = make_int2(st, s_cnt[base + i]);
    }
    __syncthreads();

#pragma unroll
    for (int i = 0; i < NPTS / 1024; i++) {
        int slot = atomicAdd(&s_start[mycell[i]], 1);
        g_pts4[slot] = make_float4(loc[i].x, loc[i].y,
                                   __int_as_float(tid + i * 1024), 0.0f);
    }
}

// ======================= K2: search =======================
#define STPB 1024
#define SNBLK 148

extern __shared__ char smem_dyn[];     // float4 s_pts[NPTS] + int2 s_cell[NCELL]

// Per-lane sorted top-6 insert (exact per-lane; no warp interaction).
__device__ __forceinline__ void ins6(ull* b, float d2, unsigned pid) {
    ull key = ((ull)__float_as_uint(d2) << 32) | pid;
    if (key < b[5]) {
        b[5] = key;
#pragma unroll
        for (int t = 5; t > 0; t--) {
            if (b[t] < b[t - 1]) { ull tmp = b[t]; b[t] = b[t - 1]; b[t - 1] = tmp; }
        }
    }
}

// ADVANCING warp-uniform upper bound on the global 6th-best d2: 6 REDUX
// rounds; each round the winning lane(s) advance to their next list entry
// (ties advance together -> duplicates counted once -> 6th DISTINCT value,
// which is >= v6: safe, and tight). Static select chain avoids spills.
__device__ __forceinline__ float ub6(const ull* b) {
    unsigned h1 = (unsigned)(b[1] >> 32), h2 = (unsigned)(b[2] >> 32);
    unsigned h3 = (unsigned)(b[3] >> 32), h4 = (unsigned)(b[4] >> 32);
    unsigned h5 = (unsigned)(b[5] >> 32);
    unsigned v = (unsigned)(b[0] >> 32);
    int idx = 0;
    unsigned m = 0;
#pragma unroll
    for (int r = 0; r < 6; r++) {
        m = __reduce_min_sync(FULLM, v);
        if (v == m) {
            idx++;
            v = (idx == 1) ? h1 : (idx == 2) ? h2 : (idx == 3) ? h3
              : (idx == 4) ? h4 : (idx == 5) ? h5 : 0xFFFFFFFFu;
        }
    }
    return (m >= 0x7F800000u) ? FINF : __uint_as_float(m);
}

// Exact final extraction: 6 rounds of two-phase REDUX (min d2-bits, then min
// pid among ties). Unique keys -> exactly one owner shifts. Lane r -> rank r.
__device__ __forceinline__ ull extract_rank(ull* b, int lane) {
    ull myrk = SENT;
#pragma unroll
    for (int r = 0; r < 6; r++) {
        unsigned hi = (unsigned)(b[0] >> 32);
        unsigned mhi = __reduce_min_sync(FULLM, hi);
        unsigned lo = (hi == mhi) ? (unsigned)(b[0] & 0xFFFFFFFFULL)
                                  : 0xFFFFFFFFu;
        unsigned mlo = __reduce_min_sync(FULLM, lo);
        ull win = ((ull)mhi << 32) | mlo;
        if (lane == r) myrk = win;
        if (b[0] == win) {
            b[0] = b[1]; b[1] = b[2]; b[2] = b[3];
            b[3] = b[4]; b[4] = b[5]; b[5] = SENT;
        }
    }
    return myrk;
}

__global__ __launch_bounds__(STPB, 1)
void search_kernel(const float* __restrict__ outputs,
                   float* __restrict__ out) {
    float4* s_pts  = (float4*)smem_dyn;
    int2*   s_cell = (int2*)(smem_dyn + NPTS * sizeof(float4));

    const int tid = threadIdx.x;
    const int lane = tid & 31;

    for (int i = tid; i < NPTS; i += STPB) s_pts[i] = g_pts4[i];
    for (int i = tid; i < NCELL; i += STPB) s_cell[i] = g_cellinfo[i];
    __syncthreads();

    const float minx = g_minx, miny = g_miny;
    const float invw = g_invw, invh = g_invh;
    const float cw = g_cwmin;

    // ---- dynamic query pool: warps pop until drained (tail-balanced) ----
    for (;;) {
        unsigned q;
        if (lane == 0) q = atomicAdd(&g_qhead, 1u);
        q = __shfl_sync(FULLM, q, 0);
        if (q >= NPTS) break;

        const float4 Q = s_pts[q];
        const float qx = Q.x, qy = Q.y;
        const unsigned qpid = (unsigned)__float_as_int(Q.z);
        const int cx = min(max((int)((qx - minx) * invw), 0), G - 1);
        const int cy = min(max((int)((qy - miny) * invh), 0), G - 1);

        ull b[6];
#pragma unroll
        for (int t = 0; t < 6; t++) b[t] = SENT;

        // ---- disk D=1: flattened union of <=3 contiguous row ranges ----
        {
            int xa = max(cx - 1, 0), xb = min(cx + 1, G - 1);
            int ya = max(cy - 1, 0), yb = min(cy + 1, G - 1);
            int s0 = 0, l0 = 0, s1 = 0, l1 = 0, s2 = 0, l2 = 0;
            {
                int2 c0 = s_cell[ya * G + xa];
                int2 c1 = s_cell[ya * G + xb];
                s0 = c0.x; l0 = c1.x + c1.y - c0.x;
            }
            if (ya + 1 <= yb) {
                int2 c0 = s_cell[(ya + 1) * G + xa];
                int2 c1 = s_cell[(ya + 1) * G + xb];
                s1 = c0.x; l1 = c1.x + c1.y - c0.x;
            }
            if (ya + 2 <= yb) {
                int2 c0 = s_cell[(ya + 2) * G + xa];
                int2 c1 = s_cell[(ya + 2) * G + xb];
                s2 = c0.x; l2 = c1.x + c1.y - c0.x;
            }
            int o1 = l0, o2 = l0 + l1, tot = o2 + l2;
            for (int t = lane; t < tot; t += 32) {
                int j;
                if (t < o1)      j = s0 + t;
                else if (t < o2) j = s1 + (t - o1);
                else             j = s2 + (t - o2);
                float4 P = s_pts[j];
                float dx = qx - P.x, dy = qy - P.y;
                float d2 = fmaf(dx, dx, dy * dy);
                ins6(b, d2, (unsigned)__float_as_int(P.z));
            }
        }
        float th = ub6(b);   // warp-uniform upper bound on v6 (tight)

        // ---- expanding rings, lane-per-cell, ub-gated termination ----
        int D = 1;
        while (D < G) {
            float bnd = (float)D * cw;
            if (th <= bnd * bnd) break;   // ub >= v6 -> exact termination
            const int d = D + 1;
            const int ncells = 8 * d;
            bool dirty = false;
            for (int tb = 0; tb < ncells; tb += 32) {
                int t = tb + lane;
                if (t < ncells) {
                    int x, y;
                    int rowspan = 2 * d + 1;
                    if (t < 2 * rowspan) {
                        int row = t / rowspan, k = t % rowspan;
                        x = cx - d + k;
                        y = row ? cy + d : cy - d;
                    } else {
                        int t2 = t - 2 * rowspan;
                        int colspan = 2 * d - 1;
                        int col = t2 / colspan, k = t2 % colspan;
                        x = col ? cx + d : cx - d;
                        y = cy - d + 1 + k;
                    }
                    if ((unsigned)x < G && (unsigned)y < G) {
                        int2 ci = s_cell[y * G + x];
                        int e = ci.x + ci.y;
                        for (int j = ci.x; j < e; j++) {
                            float4 P = s_pts[j];
                            float dx = qx - P.x, dy = qy - P.y;
                            float d2 = fmaf(dx, dx, dy * dy);
                            if (d2 <= th) {   // ub gate: conservative, safe
                                ins6(b, d2, (unsigned)__float_as_int(P.z));
                                dirty = true;
                            }
                        }
                    }
                }
            }
            if (__ballot_sync(FULLM, dirty)) th = ub6(b);
            D = d;
        }

        // ---- exact extraction once; rank 0 = self; lanes 1..5 = nbrs ----
        ull myrk = extract_rank(b, lane);
        float s = 0.0f;
        if (lane >= 1 && lane <= KNN) {
            int nb = (int)(myrk & 0xFFFFFFFFULL);
            const float4* oq = (const float4*)(outputs + (size_t)qpid * NCH);
            const float4* on = (const float4*)(outputs + (size_t)nb * NCH);
            float acc = 0.0f;
#pragma unroll
            for (int c = 0; c < NCH / 4; c++) {
                float4 a = oq[c];
                float4 bb = on[c];
                float d;
                d = a.x - bb.x; acc = fmaf(d, d, acc);
                d = a.y - bb.y; acc = fmaf(d, d, acc);
                d = a.z - bb.z; acc = fmaf(d, d, acc);
                d = a.w - bb.w; acc = fmaf(d, d, acc);
            }
            s = sqrtf(acc);
        }
#pragma unroll
        for (int off = 16; off > 0; off >>= 1)
            s += __shfl_xor_sync(FULLM, s, off);
        if (lane == 0) g_partial[qpid] = s;
    }

    // ---- fused final reduction: last CTA, fixed order ----
    __syncthreads();
    __shared__ bool is_last;
    if (tid == 0) {
        __threadfence();
        unsigned tk = atomicAdd(&g_ticket, 1);
        is_last = (tk == SNBLK - 1);
    }
    __syncthreads();
    if (is_last) {
        __threadfence();
        float acc = 0.0f;
        for (int j = tid; j < NPTS; j += STPB) acc += g_partial[j];
        __shared__ float sm[STPB];
        sm[tid] = acc;
        __syncthreads();
        for (int st = STPB / 2; st > 0; st >>= 1) {
            if (tid < st) sm[tid] += sm[tid + st];
            __syncthreads();
        }
        if (tid == 0) {
            out[0] = sm[0] / (float)(NPTS * KNN);
            g_ticket = 0;   // reset for next graph replay
        }
    }
}

extern "C" void kernel_launch(void* const* d_in, const int* in_sizes, int n_in,
                              void* d_out, int out_size) {
    const float*  outputs = (const float*)d_in[0];
    const float2* points  = (const float2*)d_in[1];
    float* out = (float*)d_out;

    const int smem_bytes = NPTS * sizeof(float4) + NCELL * sizeof(int2);
    cudaFuncSetAttribute(search_kernel,
                         cudaFuncAttributeMaxDynamicSharedMemorySize,
                         smem_bytes);
    build_kernel<<<1, 1024>>>(points);
    search_kernel<<<SNBLK, STPB, smem_bytes>>>(outputs, out);
}